// round 8
// baseline (speedup 1.0000x reference)
#include <cuda_runtime.h>
#include <math.h>

#define HIDDEN   2048
#define NQ       8
#define HD       256
#define QKV_ROWS 2560   // (8 + 2) * 256
#define SEQ      8192
#define LAYER    5
#define CHUNK    32
#define NCHUNK   256    // SEQ / CHUNK
#define GEMV_GRID 592
#define STAGE_F4 1024   // float4 per stage = 2 rows * 2048 floats

// ---------------- scratch (device globals; no allocation) ----------------
__device__ __align__(16) float g_qkv[QKV_ROWS];
__device__ __align__(16) float g_part[NCHUNK * NQ * HD];
__device__ __align__(16) float g_l[NCHUNK * NQ];
__device__ __align__(16) float g_attn[NQ * HD];

__device__ __forceinline__ float warp_sum(float v) {
#pragma unroll
    for (int o = 16; o; o >>= 1) v += __shfl_xor_sync(0xffffffffu, v, o);
    return v;
}
__device__ __forceinline__ float warp_max(float v) {
#pragma unroll
    for (int o = 16; o; o >>= 1) v = fmaxf(v, __shfl_xor_sync(0xffffffffu, v, o));
    return v;
}
__device__ __forceinline__ float dot4(float4 a, float4 b) {
    return a.x * b.x + a.y * b.y + a.z * b.z + a.w * b.w;
}

// ---------------- GEMV: cp.async double-buffered smem staging --------------
// Stage = 2 consecutive rows (16 KB, contiguous in W). While stage s is being
// dotted from smem, stage s+1's cp.async traffic is in flight -> the DRAM
// pipe never drains inside a block. Grid-stride over row-pairs.
__global__ void __launch_bounds__(256, 4)
gemv_kernel(const float* __restrict__ W,
            const float* __restrict__ x,
            float* __restrict__ y, int rowPairs) {
    __shared__ float4 sx[HIDDEN / 4];          // 8 KB
    __shared__ float4 sbuf[2][STAGE_F4];       // 32 KB
    __shared__ float  swarp[8];

    int tid  = threadIdx.x;
    int warp = tid >> 5, lane = tid & 31;
    int stride = gridDim.x;

    // issue a stage: 4 cp.async of 16B per thread (always commit, even empty)
    auto issue = [&](int slot, int rp) {
        if (rp < rowPairs) {
            const float4* src = reinterpret_cast<const float4*>(W) + (size_t)rp * STAGE_F4;
            unsigned dst = (unsigned)__cvta_generic_to_shared(&sbuf[slot][0]);
#pragma unroll
            for (int k = 0; k < 4; k++) {
                unsigned d = dst + (unsigned)((tid + 256 * k) * 16);
                const float4* s = src + tid + 256 * k;
                asm volatile("cp.async.cg.shared.global [%0], [%1], 16;\n"
                             :: "r"(d), "l"(s));
            }
        }
        asm volatile("cp.async.commit_group;\n");
    };

    int rp = blockIdx.x;
    issue(0, rp);
    issue(1, rp + stride);

    // stage x while the first W stages are in flight
    {
        const float4* x4 = reinterpret_cast<const float4*>(x);
        sx[tid]       = __ldg(&x4[tid]);
        sx[tid + 256] = __ldg(&x4[tid + 256]);
    }

    int slot = 0;
    int rl = tid >> 7;            // row within pair
    int t  = tid & 127;           // thread within row
    while (rp < rowPairs) {
        asm volatile("cp.async.wait_group 1;\n");
        __syncthreads();          // stage 'slot' visible to all; sx ready

        float4* buf = &sbuf[slot][rl * 512];
        float acc = dot4(buf[t],       sx[t])
                  + dot4(buf[t + 128], sx[t + 128])
                  + dot4(buf[t + 256], sx[t + 256])
                  + dot4(buf[t + 384], sx[t + 384]);
        acc = warp_sum(acc);
        if (lane == 0) swarp[warp] = acc;
        __syncthreads();          // compute reads done -> safe to refill slot

        if (tid < 2)
            y[rp * 2 + tid] = swarp[4 * tid] + swarp[4 * tid + 1] +
                              swarp[4 * tid + 2] + swarp[4 * tid + 3];

        issue(slot, rp + 2 * stride);
        rp += stride;
        slot ^= 1;
    }
}

// ---------------- fused attention: norm+rope + scores + exp + partial PV ---
__global__ void fused_attn_kernel(const float* __restrict__ kc,
                                  const float* __restrict__ vc,
                                  const float* __restrict__ mask,
                                  const float* __restrict__ cosv,
                                  const float* __restrict__ sinv,
                                  const float* __restrict__ qw,
                                  const float* __restrict__ kw,
                                  const int* __restrict__ kvidx) {
    __shared__ float sq[NQ * HD];
    __shared__ float sk[HD];
    __shared__ float sexp[CHUNK * NQ];
    __shared__ float smask[CHUNK];
    __shared__ int   sany;

    int c    = blockIdx.x;
    int tid  = threadIdx.x;
    int warp = tid >> 5, lane = tid & 31;
    int s0   = c * CHUNK;

    if (tid == 0) sany = 0;
    __syncthreads();
    if (tid < CHUNK) {
        float m = mask[s0 + tid];
        smask[tid] = m;
        if (m > -1e8f) atomicOr(&sany, 1);
    }
    __syncthreads();
    if (!sany) {
        if (tid < NQ) g_l[c * NQ + tid] = 0.0f;
        return;
    }

    // --- norm + rope (recomputed per block; L2-resident) -------------------
    for (int head = warp; head < 9; head += 8) {
        float x[8];
#pragma unroll
        for (int j = 0; j < 8; j++) x[j] = g_qkv[head * HD + lane + 32 * j];
        float mv = 0.f;
#pragma unroll
        for (int j = 0; j < 8; j++) mv = fmaxf(mv, fabsf(x[j]));
        mv = warp_max(mv);
        mv = fmaxf(mv, 5.9604644775390625e-8f);   // 2^-24
        float ss = 0.f, xs[8];
#pragma unroll
        for (int j = 0; j < 8; j++) { xs[j] = x[j] / mv; ss += xs[j] * xs[j]; }
        ss = warp_sum(ss);
        float rs = rsqrtf(ss);
        const float* wv = (head < NQ) ? qw : kw;
        float y[8];
#pragma unroll
        for (int j = 0; j < 8; j++) {
            int d = lane + 32 * j;
            y[j] = rs * 16.0f * xs[j] * (1.0f + wv[d]);
        }
#pragma unroll
        for (int j = 0; j < 8; j++) {
            int d = lane + 32 * j;
            float rot = (j < 4) ? -y[j ^ 4] : y[j ^ 4];
            float out = y[j] * cosv[d] + rot * sinv[d];
            if (head < NQ) sq[head * HD + d] = out * 0.0625f;  // * 256^-0.5
            else           sk[d] = out;
        }
    }
    __syncthreads();

    int pos = *kvidx;
    const float* kbase = kc + (size_t)LAYER * SEQ * HD;

    // --- scores -> softcap -> exp (warp per 4 positions, batched) ----------
    {
        float acc[4][NQ];
        const float4* k4p[4];
#pragma unroll
        for (int r = 0; r < 4; r++) {
            int sl = warp * 4 + r;
            int s = s0 + sl;
            const float* krow = (s == pos) ? sk : (kbase + (size_t)s * HD);
            k4p[r] = reinterpret_cast<const float4*>(krow);
#pragma unroll
            for (int h = 0; h < NQ; h++) acc[r][h] = 0.f;
        }
#pragma unroll
        for (int i = 0; i < 2; i++) {
            int idx = i * 32 + lane;
            float4 kv[4];
#pragma unroll
            for (int r = 0; r < 4; r++) kv[r] = k4p[r][idx];
#pragma unroll
            for (int h = 0; h < NQ; h++) {
                const float4* q4 = reinterpret_cast<const float4*>(&sq[h * HD]);
                float4 qv = q4[idx];
#pragma unroll
                for (int r = 0; r < 4; r++)
                    acc[r][h] += dot4(kv[r], qv);
            }
        }
#pragma unroll
        for (int r = 0; r < 4; r++) {
            int sl = warp * 4 + r;
            float m = smask[sl];
#pragma unroll
            for (int h = 0; h < NQ; h++) {
                float v = warp_sum(acc[r][h]);
                if (lane == h)
                    sexp[sl * NQ + h] = (m < -1e8f) ? 0.0f
                                      : expf(tanhf(v * 0.02f) * 50.0f + m);
            }
        }
    }
    __syncthreads();

    // --- per-head exp-sum ---------------------------------------------------
    if (warp < NQ) {
        float l = sexp[lane * NQ + warp];
        l = warp_sum(l);
        if (lane == 0) g_l[c * NQ + warp] = l;
    }

    // --- partial P.V (thread = dim d) ---------------------------------------
    const float* vbase = vc + (size_t)LAYER * SEQ * HD;
    const float* vnew  = g_qkv + 9 * HD;
    int d = tid;
    float acc[NQ] = {0, 0, 0, 0, 0, 0, 0, 0};
#pragma unroll 8
    for (int sl = 0; sl < CHUNK; sl++) {
        int s = s0 + sl;
        float v = (s == pos) ? vnew[d] : __ldcs(&vbase[(size_t)s * HD + d]);
#pragma unroll
        for (int h = 0; h < NQ; h++) acc[h] += sexp[sl * NQ + h] * v;
    }
#pragma unroll
    for (int h = 0; h < NQ; h++)
        g_part[(c * NQ + h) * HD + d] = acc[h];
}

// ---------------- combine partials across chunks ---------------------------
__global__ void combine_kernel() {
    int h  = blockIdx.x;
    int d0 = blockIdx.y * 32;
    int tid = threadIdx.x;
    int g  = tid >> 5;          // chunk group 0..7
    int dl = tid & 31;
    int d  = d0 + dl;

    __shared__ float sl[NCHUNK];
    sl[tid] = g_l[tid * NQ + h];
    __syncthreads();

    float acc = 0.f, L = 0.f;
#pragma unroll
    for (int k = 0; k < 32; k++) {
        int c = g * 32 + k;
        float l = sl[c];
        if (l > 0.f) {
            L += l;
            acc += g_part[(c * NQ + h) * HD + d];
        }
    }
    __shared__ float sacc[8][32];
    __shared__ float sLr[8][32];
    sacc[g][dl] = acc;
    sLr[g][dl]  = L;
    __syncthreads();
    if (g == 0) {
        float a = 0.f, Lt = 0.f;
#pragma unroll
        for (int k = 0; k < 8; k++) { a += sacc[k][dl]; Lt += sLr[k][dl]; }
        g_attn[h * HD + d] = a / Lt;
    }
}

// ---------------- launch ----------------------------------------------------
extern "C" void kernel_launch(void* const* d_in, const int* in_sizes, int n_in,
                              void* d_out, int out_size) {
    const float* hs   = (const float*)d_in[0];   // hidden_states (2048)
    const float* cosv = (const float*)d_in[1];   // cos (256)
    const float* sinv = (const float*)d_in[2];   // sin (256)
    const int*   kvix = (const int*)  d_in[3];   // kv_write_indices (1)
    const float* kc   = (const float*)d_in[4];   // k_cache
    const float* vc   = (const float*)d_in[5];   // v_cache
    const float* mask = (const float*)d_in[6];   // mask (8192)
    const float* qkvw = (const float*)d_in[7];   // qkv_w (2560x2048)
    const float* ow   = (const float*)d_in[8];   // o_w   (2048x2048)
    const float* qnw  = (const float*)d_in[9];   // q_norm_w (256)
    const float* knw  = (const float*)d_in[10];  // k_norm_w (256)
    float* out = (float*)d_out;

    void* p_qkv = nullptr;
    void* p_attn = nullptr;
    cudaGetSymbolAddress(&p_qkv, g_qkv);
    cudaGetSymbolAddress(&p_attn, g_attn);

    gemv_kernel<<<GEMV_GRID, 256>>>(qkvw, hs, (float*)p_qkv, QKV_ROWS / 2);
    fused_attn_kernel<<<NCHUNK, 256>>>(kc, vc, mask, cosv, sinv, qnw, knw, kvix);
    combine_kernel<<<dim3(NQ, 8), 256>>>();
    gemv_kernel<<<GEMV_GRID, 256>>>(ow, (const float*)p_attn, out, HIDDEN / 2);
}